// round 6
// baseline (speedup 1.0000x reference)
#include <cuda_runtime.h>

#define NT 128
typedef unsigned long long u64;

__device__ __forceinline__ u64 pk2(float x, float y) {
    u64 r; asm("mov.b64 %0,{%1,%2};" : "=l"(r) : "f"(x), "f"(y)); return r;
}
__device__ __forceinline__ void upk2(u64 v, float& x, float& y) {
    asm("mov.b64 {%0,%1},%2;" : "=f"(x), "=f"(y) : "l"(v));
}
__device__ __forceinline__ u64 ffma2(u64 a, u64 b, u64 c) {
    u64 d; asm("fma.rn.f32x2 %0,%1,%2,%3;" : "=l"(d) : "l"(a), "l"(b), "l"(c)); return d;
}

// packed butterfly over pair-index bit B (both lanes of the f32x2 move together)
template <int B>
__device__ __forceinline__ void vstage(u64* v, float t) {
    u64 tp = pk2(t, t), tn = pk2(-t, -t);
#pragma unroll
    for (int a = 0; a < 32; ++a)
        if (!(a & (1 << B))) {
            u64 A = v[a], Bv = v[a | (1 << B)];
            v[a]            = ffma2(tn, Bv, A);   // A - t*B
            v[a | (1 << B)] = ffma2(tp, A, Bv);   // t*A + B
        }
}

// src L-bits (idx bits 1..5, pre-parity) of the entangling gather for dst pair j
__device__ constexpr int QL(int j) {
    int j0 = j & 1, j1 = (j >> 1) & 1, j2 = (j >> 2) & 1, j3 = (j >> 3) & 1, j4 = (j >> 4) & 1;
    return (j0 ^ j1) | ((j1 ^ j2 ^ j3) << 1) | ((j2 ^ j3) << 2) | ((j3 ^ j4) << 3) | (j4 << 4);
}

__global__ void __launch_bounds__(NT)
qsim_kernel(const float* __restrict__ feats,
            const float* __restrict__ qp,
            float* __restrict__ out)
{
    // layout: addrF(idx) = H*64 + ((L5 ^ (H&31))<<1 | d0); H=idx>>6, L5=(idx>>1)&31, d0=idx&1
    __shared__ float2 st2s[4096];   // 2 rows x 2048 float2
    float* stf = reinterpret_cast<float*>(st2s);
    __shared__ float tt[240];
    __shared__ float wred[4], gred[4], oscale[2];
    __shared__ float rsum[4][12];

    const int t    = threadIdx.x;
    const int row  = t >> 6;
    const int u    = t & 63;
    const int lane = t & 31;
    const int b    = blockIdx.x;

    // tan table + global cos product (cos factors folded into output scale G^2)
    float gpart = 1.0f;
    for (int i = t; i < 240; i += NT) {
        float s, c; sincosf(0.5f * qp[12 + i], &s, &c);
        tt[i] = s / c; gpart *= c;
    }
#pragma unroll
    for (int o = 16; o; o >>= 1) gpart *= __shfl_xor_sync(~0u, gpart, o);
    if (lane == 0) gred[t >> 5] = gpart;

    // embedding (unnormalized; 1/||s||^2 folded into output scale)
    const float2* f2 = reinterpret_cast<const float2*>(feats + (size_t)(b * 2 + row) * 2048);
    float2* row2 = st2s + (row << 11);
    const float PIO2 = 1.5707963267948966f;
    float acc = 8.0f;  // padding ssq share: 32 * 0.25
#pragma unroll
    for (int v = 0; v < 16; ++v) {
        int p = v * 64 + u;
        float2 x = f2[p];
        float2 y = make_float2(tanhf(x.x) * PIO2, tanhf(x.y) * PIO2);
        acc += y.x * y.x + y.y * y.y;
        int h5 = p >> 5;
        row2[h5 * 32 + ((p & 31) ^ (h5 & 31))] = y;
    }
#pragma unroll
    for (int v = 16; v < 32; ++v) {
        int p = v * 64 + u;
        int h5 = p >> 5;
        row2[h5 * 32 + ((p & 31) ^ (h5 & 31))] = make_float2(0.5f, 0.5f);
    }
#pragma unroll
    for (int o = 16; o; o >>= 1) acc += __shfl_xor_sync(~0u, acc, o);
    if (lane == 0) wred[t >> 5] = acc;
    __syncthreads();
    if (t < 2) {
        float G = gred[0] * gred[1] * gred[2] * gred[3];
        oscale[t] = (G * G) / (wred[2 * t] + wred[2 * t + 1]);
    }

    // per-thread constants
    int u0 = u & 1, u1 = (u >> 1) & 1, u2b = (u >> 2) & 1;
    int u3 = (u >> 3) & 1, u4 = (u >> 4) & 1, u5 = (u >> 5) & 1;
    int Hs = (u0 ^ u1 ^ u2b)
           | ((u1 ^ u2b) << 1)
           | ((u2b ^ u3 ^ u4) << 2)
           | ((u3 ^ u4) << 3)
           | ((u4 ^ u5) << 4)
           | (u5 << 5);
    int xm = (u0 ? 0x18 : 0) ^ (Hs & 31);   // parity term (src bits 4,5) + swizzle
    float2* gbase = row2 + Hs * 32;          // pass-1 gather base
    float2* sbase = row2 + u * 32;           // pass-1 store base
    int sm = u & 31;
    float* rowf = stf + (row << 12);

#pragma unroll 1
    for (int L = 0; L < 20; ++L) {
        const float* tc = &tt[L * 12];

        // ===== pass 1: entangling gather + RY qubits 11..6 (idx bits 0..5) =====
        u64 vr[32];
        float t11 = tc[11];
#pragma unroll
        for (int j = 0; j < 32; ++j) {
            float2 w = gbase[QL(j) ^ xm];
            float x0, x1;  // x0 = src of dst(d0=0); mem .x holds q0=0 <=> r0 = j0^j1
            if (((j ^ (j >> 1)) & 1) == 0) { x0 = w.x; x1 = w.y; }
            else                            { x0 = w.y; x1 = w.x; }
            // fold qubit-11 stage (d0) into the load
            vr[j] = pk2(fmaf(-t11, x1, x0), fmaf(t11, x0, x1));
        }
        vstage<0>(vr, tc[10]);
        vstage<1>(vr, tc[9]);
        vstage<2>(vr, tc[8]);
        vstage<3>(vr, tc[7]);
        vstage<4>(vr, tc[6]);
        __syncthreads();   // all gathers complete before in-place overwrite
#pragma unroll
        for (int j = 0; j < 32; ++j) {
            float x, y; upk2(vr[j], x, y);
            sbase[j ^ sm] = make_float2(x, y);
        }
        __syncthreads();

        // ===== pass 2: RY qubits 5..0 (idx bits 6..11), in-place =====
        u64 vp[32];
        float t5 = tc[5];
#pragma unroll
        for (int a = 0; a < 32; ++a) {
            float x0 = rowf[(2 * a) * 64     + (u ^ ((4 * a)     & 62))];
            float x1 = rowf[(2 * a + 1) * 64 + (u ^ ((4 * a + 2) & 62))];
            // fold qubit-5 stage (idx bit 6) into the load
            vp[a] = pk2(fmaf(-t5, x1, x0), fmaf(t5, x0, x1));
        }
        vstage<0>(vp, tc[4]);
        vstage<1>(vp, tc[3]);
        vstage<2>(vp, tc[2]);
        vstage<3>(vp, tc[1]);
        vstage<4>(vp, tc[0]);

        if (L < 19) {
#pragma unroll
            for (int a = 0; a < 32; ++a) {
                float x, y; upk2(vp[a], x, y);
                rowf[(2 * a) * 64     + (u ^ ((4 * a)     & 62))] = x;
                rowf[(2 * a + 1) * 64 + (u ^ ((4 * a + 2) & 62))] = y;
            }
            __syncthreads();
        } else {
            // ===== expvals straight from registers =====
            // component (.x/.y) = idx bit 6 (qubit 5); a bits 0..4 = idx bits 7..11 (qubits 4..0)
            float S = 0.f, Ty = 0.f, T0 = 0.f, T1 = 0.f, T2 = 0.f, T3 = 0.f, T4 = 0.f;
#pragma unroll
            for (int a = 0; a < 32; ++a) {
                float x, y; upk2(vp[a], x, y);
                float px = x * x, py = y * y, ps = px + py;
                S += ps; Ty += py;
                if (a & 1)  T0 += ps;
                if (a & 2)  T1 += ps;
                if (a & 4)  T2 += ps;
                if (a & 8)  T3 += ps;
                if (a & 16) T4 += ps;
            }
            float val[12];
            val[0] = S - 2.f * T4;   // qubit 0 = idx bit 11 = a bit 4
            val[1] = S - 2.f * T3;
            val[2] = S - 2.f * T2;
            val[3] = S - 2.f * T1;
            val[4] = S - 2.f * T0;
            val[5] = S - 2.f * Ty;   // qubit 5 = idx bit 6 = component
#pragma unroll
            for (int q = 6; q < 12; ++q)
                val[q] = ((u >> (11 - q)) & 1) ? -S : S;   // thread bits
#pragma unroll
            for (int q = 0; q < 12; ++q) {
#pragma unroll
                for (int o = 16; o; o >>= 1)
                    val[q] += __shfl_xor_sync(~0u, val[q], o);
            }
            if (lane == 0) {
#pragma unroll
                for (int q = 0; q < 12; ++q) rsum[t >> 5][q] = val[q];
            }
        }
    }

    __syncthreads();
    if (t < 24) {
        int r = t / 12, q = t % 12;
        out[(size_t)(b * 2 + r) * 12 + q] =
            (rsum[2 * r][q] + rsum[2 * r + 1][q]) * oscale[r];
    }
}

extern "C" void kernel_launch(void* const* d_in, const int* in_sizes, int n_in,
                              void* d_out, int out_size) {
    const float* feats = (const float*)d_in[0];
    const float* qp    = (const float*)d_in[1];
    float* out         = (float*)d_out;
    qsim_kernel<<<2048, NT>>>(feats, qp, out);
}

// round 7
// speedup vs baseline: 1.0585x; 1.0585x over previous
#include <cuda_runtime.h>

#define NT 64
typedef unsigned long long u64;

__device__ __forceinline__ u64 pk2(float x, float y) {
    u64 r; asm("mov.b64 %0,{%1,%2};" : "=l"(r) : "f"(x), "f"(y)); return r;
}
__device__ __forceinline__ void upk2(u64 v, float& x, float& y) {
    asm("mov.b64 {%0,%1},%2;" : "=f"(x), "=f"(y) : "l"(v));
}
__device__ __forceinline__ u64 ffma2(u64 a, u64 b, u64 c) {
    u64 d; asm("fma.rn.f32x2 %0,%1,%2,%3;" : "=l"(d) : "l"(a), "l"(b), "l"(c)); return d;
}

// packed butterfly over pair-index bit B (both lanes of the f32x2 move together)
template <int B>
__device__ __forceinline__ void vstage(u64* v, float t) {
    u64 tp = pk2(t, t), tn = pk2(-t, -t);
#pragma unroll
    for (int a = 0; a < 32; ++a)
        if (!(a & (1 << B))) {
            u64 A = v[a], Bv = v[a | (1 << B)];
            v[a]            = ffma2(tn, Bv, A);   // A - t*B
            v[a | (1 << B)] = ffma2(tp, A, Bv);   // t*A + B
        }
}

// src L-bits (idx bits 1..5, pre-parity) of the entangling gather for dst pair j
__device__ constexpr int QL(int j) {
    int j0 = j & 1, j1 = (j >> 1) & 1, j2 = (j >> 2) & 1, j3 = (j >> 3) & 1, j4 = (j >> 4) & 1;
    return (j0 ^ j1) | ((j1 ^ j2 ^ j3) << 1) | ((j2 ^ j3) << 2) | ((j3 ^ j4) << 3) | (j4 << 4);
}

__global__ void __launch_bounds__(NT, 8)
qsim_kernel(const float* __restrict__ feats,
            const float* __restrict__ qp,
            float* __restrict__ out)
{
    // layout: addrF(idx) = H*64 + ((L5 ^ (H&31))<<1 | d0); H=idx>>6, L5=(idx>>1)&31, d0=idx&1
    __shared__ float2 st2s[2048];    // one row: 4096 floats
    float* stf = reinterpret_cast<float*>(st2s);
    __shared__ float tt[240];
    __shared__ float wred[2], gred[2];
    __shared__ float oscale_s;
    __shared__ float rsum[2][12];

    const int u    = threadIdx.x;    // 0..63
    const int lane = u & 31;
    const int b    = blockIdx.x;

    // tan table + global cos product (cos factors folded into output scale G^2)
    float gpart = 1.0f;
    for (int i = u; i < 240; i += NT) {
        float s, c; sincosf(0.5f * qp[12 + i], &s, &c);
        tt[i] = s / c; gpart *= c;
    }
#pragma unroll
    for (int o = 16; o; o >>= 1) gpart *= __shfl_xor_sync(~0u, gpart, o);
    if (lane == 0) gred[u >> 5] = gpart;

    // embedding (unnormalized; 1/||s||^2 folded into output scale)
    const float2* f2 = reinterpret_cast<const float2*>(feats + (size_t)b * 2048);
    const float PIO2 = 1.5707963267948966f;
    float acc = 8.0f;  // padding ssq share: 32 * 0.25
#pragma unroll
    for (int v = 0; v < 16; ++v) {
        int p = v * 64 + u;
        float2 x = f2[p];
        float2 y = make_float2(tanhf(x.x) * PIO2, tanhf(x.y) * PIO2);
        acc += y.x * y.x + y.y * y.y;
        int h5 = p >> 5;
        st2s[h5 * 32 + ((p & 31) ^ (h5 & 31))] = y;
    }
#pragma unroll
    for (int v = 16; v < 32; ++v) {
        int p = v * 64 + u;
        int h5 = p >> 5;
        st2s[h5 * 32 + ((p & 31) ^ (h5 & 31))] = make_float2(0.5f, 0.5f);
    }
#pragma unroll
    for (int o = 16; o; o >>= 1) acc += __shfl_xor_sync(~0u, acc, o);
    if (lane == 0) wred[u >> 5] = acc;
    __syncthreads();
    if (u == 0) {
        float G = gred[0] * gred[1];
        oscale_s = (G * G) / (wred[0] + wred[1]);
    }

    // per-thread constants: pass-1 source thread-block (entangling map on idx bits 6..11)
    int u0 = u & 1, u1 = (u >> 1) & 1, u2b = (u >> 2) & 1;
    int u3 = (u >> 3) & 1, u4 = (u >> 4) & 1, u5 = (u >> 5) & 1;
    int Hs = (u0 ^ u1 ^ u2b)
           | ((u1 ^ u2b) << 1)
           | ((u2b ^ u3 ^ u4) << 2)
           | ((u3 ^ u4) << 3)
           | ((u4 ^ u5) << 4)
           | (u5 << 5);
    int xm = (u0 ? 0x18 : 0) ^ (Hs & 31);   // parity term (src bits 4,5) + swizzle
    float2* gbase = st2s + Hs * 32;          // pass-1 gather base
    float2* sbase = st2s + u * 32;           // pass-1 store base
    int sm = u & 31;

#pragma unroll 1
    for (int L = 0; L < 20; ++L) {
        const float* tc = &tt[L * 12];

        // ===== pass 1: entangling gather + RY qubits 11..6 (idx bits 0..5) =====
        u64 vr[32];
        {
            float t11 = tc[11];
            u64 tpm = pk2(-t11, t11);
#pragma unroll
            for (int j = 0; j < 32; ++j) {
                float2 w = gbase[QL(j) ^ xm];
                float x0, x1;  // x0 = src of dst(d0=0); mem .x holds q0=0 <=> r0 = j0^j1
                if (((j ^ (j >> 1)) & 1) == 0) { x0 = w.x; x1 = w.y; }
                else                            { x0 = w.y; x1 = w.x; }
                // packed fold of the qubit-11 stage: (x0 - t*x1, x1 + t*x0)
                vr[j] = ffma2(tpm, pk2(x1, x0), pk2(x0, x1));
            }
        }
        vstage<0>(vr, tc[10]);
        vstage<1>(vr, tc[9]);
        vstage<2>(vr, tc[8]);
        vstage<3>(vr, tc[7]);
        vstage<4>(vr, tc[6]);
        __syncthreads();   // all gathers complete before in-place overwrite
#pragma unroll
        for (int j = 0; j < 32; ++j) {
            float x, y; upk2(vr[j], x, y);
            sbase[j ^ sm] = make_float2(x, y);
        }
        __syncthreads();

        // ===== pass 2: RY qubits 5..0 (idx bits 6..11), thread-disjoint in-place =====
        u64 vp[32];
        {
            float t5c = tc[5];
            u64 tpm = pk2(-t5c, t5c);
#pragma unroll
            for (int a = 0; a < 32; ++a) {
                float x0 = stf[(2 * a) * 64     + (u ^ ((4 * a)     & 62))];
                float x1 = stf[(2 * a + 1) * 64 + (u ^ ((4 * a + 2) & 62))];
                // packed fold of the qubit-5 stage (idx bit 6)
                vp[a] = ffma2(tpm, pk2(x1, x0), pk2(x0, x1));
            }
        }
        vstage<0>(vp, tc[4]);
        vstage<1>(vp, tc[3]);
        vstage<2>(vp, tc[2]);
        vstage<3>(vp, tc[1]);
        vstage<4>(vp, tc[0]);

        if (L < 19) {
#pragma unroll
            for (int a = 0; a < 32; ++a) {
                float x, y; upk2(vp[a], x, y);
                stf[(2 * a) * 64     + (u ^ ((4 * a)     & 62))] = x;
                stf[(2 * a + 1) * 64 + (u ^ ((4 * a + 2) & 62))] = y;
            }
            __syncthreads();
        } else {
            // ===== expvals straight from registers =====
            // component (.x/.y) = idx bit 6 (qubit 5); a bits 0..4 = idx bits 7..11 (qubits 4..0)
            float S = 0.f, Ty = 0.f, T0 = 0.f, T1 = 0.f, T2 = 0.f, T3 = 0.f, T4 = 0.f;
#pragma unroll
            for (int a = 0; a < 32; ++a) {
                float x, y; upk2(vp[a], x, y);
                float px = x * x, py = y * y, ps = px + py;
                S += ps; Ty += py;
                if (a & 1)  T0 += ps;
                if (a & 2)  T1 += ps;
                if (a & 4)  T2 += ps;
                if (a & 8)  T3 += ps;
                if (a & 16) T4 += ps;
            }
            float val[12];
            val[0] = S - 2.f * T4;   // qubit 0 = idx bit 11 = a bit 4
            val[1] = S - 2.f * T3;
            val[2] = S - 2.f * T2;
            val[3] = S - 2.f * T1;
            val[4] = S - 2.f * T0;
            val[5] = S - 2.f * Ty;   // qubit 5 = idx bit 6 = component
#pragma unroll
            for (int q = 6; q < 12; ++q)
                val[q] = ((u >> (11 - q)) & 1) ? -S : S;   // thread bits
#pragma unroll
            for (int q = 0; q < 12; ++q) {
#pragma unroll
                for (int o = 16; o; o >>= 1)
                    val[q] += __shfl_xor_sync(~0u, val[q], o);
            }
            if (lane == 0) {
#pragma unroll
                for (int q = 0; q < 12; ++q) rsum[u >> 5][q] = val[q];
            }
        }
    }

    __syncthreads();
    if (u < 12) {
        out[(size_t)b * 12 + u] = (rsum[0][u] + rsum[1][u]) * oscale_s;
    }
}

extern "C" void kernel_launch(void* const* d_in, const int* in_sizes, int n_in,
                              void* d_out, int out_size) {
    const float* feats = (const float*)d_in[0];
    const float* qp    = (const float*)d_in[1];
    float* out         = (float*)d_out;
    qsim_kernel<<<4096, NT>>>(feats, qp, out);
}